// round 11
// baseline (speedup 1.0000x reference)
#include <cuda_runtime.h>

#define NB    32768
#define N_RX  8

// SYMS = {-3,-1,1,3}/sqrt(5)
#define S_M3 (-1.3416407864998738f)
#define S_M1 (-0.44721359549995793f)
#define S_P1 ( 0.44721359549995793f)
#define S_P3 ( 1.3416407864998738f)
#define LOG2E 1.4426950408889634f
#define LN2   0.6931471805599453f

typedef unsigned long long u64;

__device__ __forceinline__ float qsel(float a, float b, float c, float d, int i) {
    float ab = (i & 1) ? b : a;
    float cd = (i & 1) ? d : c;
    return (i & 2) ? cd : ab;
}
// rho2n*SY[i] from just rm3=rho2n*S_M3, rm1=rho2n*S_M1 (uses SY[2]=-SY[1], SY[3]=-SY[0])
__device__ __forceinline__ float qselrn(float rm3, float rm1, int i) {
    float ab = (i & 1) ? rm1 : rm3;
    float cd = (i & 1) ? -rm3 : -rm1;
    return (i & 2) ? cd : ab;
}
__device__ __forceinline__ float rowmax4(const float* v) {
    return fmaxf(fmaxf(v[0], v[1]), fmaxf(v[2], v[3]));
}
__device__ __forceinline__ float ex2a(float x) {
    float y; asm("ex2.approx.ftz.f32 %0, %1;" : "=f"(y) : "f"(x)); return y;
}
__device__ __forceinline__ float lg2a(float x) {
    float y; asm("lg2.approx.ftz.f32 %0, %1;" : "=f"(y) : "f"(x)); return y;
}
__device__ __forceinline__ float rcpa(float x) {
    float y; asm("rcp.approx.ftz.f32 %0, %1;" : "=f"(y) : "f"(x)); return y;
}
__device__ __forceinline__ u64 pk2(float lo, float hi) {
    u64 d; asm("mov.b64 %0, {%1, %2};" : "=l"(d) : "f"(lo), "f"(hi)); return d;
}
__device__ __forceinline__ void upk2(float& lo, float& hi, u64 d) {
    asm("mov.b64 {%0, %1}, %2;" : "=f"(lo), "=f"(hi) : "l"(d));
}
__device__ __forceinline__ u64 mul2(u64 a, u64 b) {
    u64 d; asm("mul.rn.f32x2 %0, %1, %2;" : "=l"(d) : "l"(a), "l"(b)); return d;
}
__device__ __forceinline__ u64 fma2(u64 a, u64 b, u64 c) {
    u64 d; asm("fma.rn.f32x2 %0, %1, %2, %3;" : "=l"(d) : "l"(a), "l"(b), "l"(c)); return d;
}

__global__ __launch_bounds__(128, 8)
void mfnet_layer_kernel(const float* __restrict__ log_qi_in,
                        const float* __restrict__ G,
                        const float* __restrict__ sqrt_2rho,
                        const float* __restrict__ alpha_ptr,
                        float* __restrict__ out)
{
    const int gtid = blockIdx.x * blockDim.x + threadIdx.x;
    const int w    = gtid >> 5;
    const int lane = gtid & 31;
    // Two items per warp: half-warps own item b = 2w + half.
    const int half = lane >> 4;
    const int hl   = lane & 15;
    const int b    = 2 * w + half;
    const int base = lane & 16;          // half-warp base lane for broadcasts

    const float alpha = __ldg(alpha_ptr);
    const float rho2  = __ldg(&sqrt_2rho[b]) * LOG2E;   // log2 units
    const float rho2n = -rho2;

    // k = i0*64 + i1*16 + i2*4 + i3 ; k = hl*16 + j
    // i0 = hl>>2 (bits 2,3), i1 = hl&3 (bits 0,1), i2 = j>>2, i3 = j&3
    const int i0 = hl >> 2;
    const int i1 = hl & 3;
    const int bit0 = hl & 1;
    const int bit1 = (hl >> 1) & 1;

    const float rm3 = rho2n * S_M3;
    const float rm1 = rho2n * S_M1;
    const float rs0 = qselrn(rm3, rm1, i0);
    const float rs1 = qselrn(rm3, rm1, i1);

    // ---- Laplace (log2 units), exp-factorized + f32x2-packed, 16 j per lane ----
    // xn = -x = t_{i2} + cb*m(i3); 2^{xn} = A_{i2} * C_{i3}
    // e = min(2^{xn},1); mterm = e*(1-0.5e); lp2[j] = Sum_r x + log2(Prod_r mterm)
    const u64 NH2  = pk2(-0.5f, -0.5f);
    const u64 ONE2 = pk2(1.0f, 1.0f);
    u64 prod2[8] = {ONE2, ONE2, ONE2, ONE2, ONE2, ONE2, ONE2, ONE2};
    float SB = 0.f, SGZ = 0.f, SGW = 0.f;
    const float4* Gv = reinterpret_cast<const float4*>(G) + (size_t)b * N_RX;
    #pragma unroll
    for (int r = 0; r < N_RX; r++) {
        float4 g = Gv[r];
        float basen = fmaf(g.x, rs0, g.y * rs1);
        SB += basen; SGZ += g.z; SGW += g.w;
        float t0 = fmaf( g.z, rm3, basen);      // rho2n*S_M3
        float t1 = fmaf( g.z, rm1, basen);      // rho2n*S_M1
        float t2 = fmaf(-g.z, rm1, basen);      // rho2n*S_P1 (operand neg, free)
        float t3 = fmaf(-g.z, rm3, basen);      // rho2n*S_P3
        float cb = g.w * rm1;                   // = -g.w*rho2n*S_P1 -> D = old iB
        float A0 = ex2a(t0), A1 = ex2a(t1), A2 = ex2a(t2), A3 = ex2a(t3);
        float D  = ex2a(cb), iD = rcpa(D);      // D = 2^{-gw*rho2n*S_P1}
        float D3 = (D * D) * D, iD3 = (iD * iD) * iD;
        u64 Ap[4] = { pk2(A0, A0), pk2(A1, A1), pk2(A2, A2), pk2(A3, A3) };
        u64 Cc[2] = { pk2(D3, D), pk2(iD, iD3) };   // (iB3,iB),(B,B3) in old naming
        #pragma unroll
        for (int p = 0; p < 8; p++) {          // p = i2*2 + (i3>>1)
            u64 v2 = mul2(Ap[p >> 1], Cc[p & 1]);
            float vlo, vhi;
            upk2(vlo, vhi, v2);
            u64 e2 = pk2(fminf(vlo, 1.0f), fminf(vhi, 1.0f));
            u64 h2 = fma2(NH2, e2, ONE2);
            prod2[p] = mul2(prod2[p], mul2(e2, h2));
        }
    }
    const float Cp  = rho2 * SGW;
    const float qz  = SGZ * rho2;
    const float nSB = -SB;
    const float SY[4] = {S_M3, S_M1, S_P1, S_P3};   // immediates
    float lp2[16];
    #pragma unroll
    for (int p = 0; p < 8; p++) {
        const int i2  = p >> 1;
        const int i3a = (p & 1) * 2;
        float T = fmaf(qz, SY[i2], nSB);            // = -Sum_r t_{i2}
        float plo, phi;
        upk2(plo, phi, prod2[p]);
        lp2[i2 * 4 + i3a]     = fmaf(Cp, SY[i3a],     T) + lg2a(fmaxf(plo, 1e-37f));
        lp2[i2 * 4 + i3a + 1] = fmaf(Cp, SY[i3a + 1], T) + lg2a(fmaxf(phi, 1e-37f));
    }

    const unsigned FULL = 0xffffffffu;
    const float oma = 1.0f - alpha;
    const float4* Lv = reinterpret_cast<const float4*>(log_qi_in) + (size_t)b * 4;

    // ---- Rows 0,1: distributed (each lane keeps only its own-index value) ----
    float4 v0 = Lv[0];
    float lq0own = qsel(v0.x, v0.y, v0.z, v0.w, i0) * LOG2E;
    float f0 = ex2a(lq0own);               // raw row, matches reference iter-0
    float4 v1 = Lv[1];
    float lq1own = qsel(v1.x, v1.y, v1.z, v1.w, i1) * LOG2E;
    float m1 = lq1own;                     // rowmax over i1 (bits 0,1)
    m1 = fmaxf(m1, __shfl_xor_sync(FULL, m1, 1));
    m1 = fmaxf(m1, __shfl_xor_sync(FULL, m1, 2));
    float f1 = ex2a(lq1own - m1);
    float S1 = f1 + __shfl_xor_sync(FULL, f1, 1);
    S1 += __shfl_xor_sync(FULL, S1, 2);

    // ---- Rows 2,3: full replication ----
    float lq[2][4], off2, off3;
    {
        float4 v = Lv[2];
        lq[0][0] = v.x * LOG2E; lq[0][1] = v.y * LOG2E;
        lq[0][2] = v.z * LOG2E; lq[0][3] = v.w * LOG2E;
        off2 = rowmax4(lq[0]);
    }
    {
        float4 v = Lv[3];
        lq[1][0] = v.x * LOG2E; lq[1][1] = v.y * LOG2E;
        lq[1][2] = v.z * LOG2E; lq[1][3] = v.w * LOG2E;
        off3 = rowmax4(lq[1]);
    }
    float e2n[4], S2, S3, ul[4];
    e2n[0] = ex2a(lq[0][0]-off2); e2n[1] = ex2a(lq[0][1]-off2);
    e2n[2] = ex2a(lq[0][2]-off2); e2n[3] = ex2a(lq[0][3]-off2);
    S2 = (e2n[0] + e2n[1]) + (e2n[2] + e2n[3]);
    {
        float e0 = ex2a(lq[1][0]-off3), e1 = ex2a(lq[1][1]-off3);
        float e2 = ex2a(lq[1][2]-off3), e3 = ex2a(lq[1][3]-off3);
        S3 = (e0 + e1) + (e2 + e3);
        #pragma unroll
        for (int c = 0; c < 4; c++)
            ul[c] = fmaf(e3, lp2[c*4+3], fmaf(e2, lp2[c*4+2], fmaf(e1, lp2[c*4+1], e0 * lp2[c*4+0])));
    }
    float sum_wl = fmaf(e2n[3], ul[3], fmaf(e2n[2], ul[2], fmaf(e2n[1], ul[1], e2n[0] * ul[0])));
    float S23 = S2 * S3;

    // ---- xi = 0 : bucket i0 (bits 2,3); reduce bits 0,1. Distributed update. ----
    float d0, S0n;
    {
        float a = f1 * sum_wl;
        a += __shfl_xor_sync(FULL, a, 1);
        a += __shfl_xor_sync(FULL, a, 2);          // own-bucket total in every lane
        float sc = alpha * rcpa(S1 * S23);
        float nv = fmaf(oma, lq0own, sc * a);
        float o = nv;
        o = fmaxf(o, __shfl_xor_sync(FULL, o, 4));
        o = fmaxf(o, __shfl_xor_sync(FULL, o, 8));
        d0 = nv - o;
        f0 = ex2a(d0);
        S0n = f0 + __shfl_xor_sync(FULL, f0, 4);
        S0n += __shfl_xor_sync(FULL, S0n, 8);
    }

    // ---- xi = 1 : bucket i1 (bits 0,1); reduce bits 2,3. Distributed update. ----
    float d1, S1n, f01;
    {
        float a = f0 * sum_wl;
        a += __shfl_xor_sync(FULL, a, 4);
        a += __shfl_xor_sync(FULL, a, 8);
        float sc = alpha * rcpa(S0n * S23);
        float nv = fmaf(oma, lq1own - m1, sc * a);
        float o = nv;
        o = fmaxf(o, __shfl_xor_sync(FULL, o, 1));
        o = fmaxf(o, __shfl_xor_sync(FULL, o, 2));
        d1 = nv - o;
        float e1n = ex2a(d1);
        S1n = e1n + __shfl_xor_sync(FULL, e1n, 1);
        S1n += __shfl_xor_sync(FULL, S1n, 2);
        f01 = f0 * e1n;
    }

    // ---- xi = 2 : bucket i2; fold onto hl bits 0,1, reduce bits 2,3. Full row. ----
    float e2w[4], S2n, S01;
    {
        float a0 = f01 * ul[0], a1 = f01 * ul[1], a2v = f01 * ul[2], a3v = f01 * ul[3];
        float kA = bit0 ? a1 : a0,   sA = bit0 ? a0 : a1;
        float kB = bit0 ? a3v : a2v, sB = bit0 ? a2v : a3v;
        float rA = kA + __shfl_xor_sync(FULL, sA, 1);
        float rB = kB + __shfl_xor_sync(FULL, sB, 1);
        float k2 = bit1 ? rB : rA,   s2 = bit1 ? rA : rB;
        float a = k2 + __shfl_xor_sync(FULL, s2, 2);    // bucket hl&3
        a += __shfl_xor_sync(FULL, a, 4);
        a += __shfl_xor_sync(FULL, a, 8);
        float b0 = __shfl_sync(FULL, a, base + 0);
        float b1 = __shfl_sync(FULL, a, base + 1);
        float b2 = __shfl_sync(FULL, a, base + 2);
        float b3 = __shfl_sync(FULL, a, base + 3);
        S01 = S0n * S1n;
        float sc = alpha * rcpa(S01 * S3);
        float o = off2;
        lq[0][0] = fmaf(oma, lq[0][0] - o, sc * b0);
        lq[0][1] = fmaf(oma, lq[0][1] - o, sc * b1);
        lq[0][2] = fmaf(oma, lq[0][2] - o, sc * b2);
        lq[0][3] = fmaf(oma, lq[0][3] - o, sc * b3);
        off2 = rowmax4(lq[0]);
        e2w[0] = ex2a(lq[0][0]-off2); e2w[1] = ex2a(lq[0][1]-off2);
        e2w[2] = ex2a(lq[0][2]-off2); e2w[3] = ex2a(lq[0][3]-off2);
        S2n = (e2w[0] + e2w[1]) + (e2w[2] + e2w[3]);
    }

    // ---- xi = 3 : bucket i3; fold + reduce bits 2,3. Full row. ----
    {
        float v0a = 0.f, v1a = 0.f, v2a = 0.f, v3a = 0.f;
        #pragma unroll
        for (int c = 0; c < 4; c++) {
            v0a = fmaf(e2w[c], lp2[c*4+0], v0a);
            v1a = fmaf(e2w[c], lp2[c*4+1], v1a);
            v2a = fmaf(e2w[c], lp2[c*4+2], v2a);
            v3a = fmaf(e2w[c], lp2[c*4+3], v3a);
        }
        v0a *= f01; v1a *= f01; v2a *= f01; v3a *= f01;
        float kA = bit0 ? v1a : v0a, sA = bit0 ? v0a : v1a;
        float kB = bit0 ? v3a : v2a, sB = bit0 ? v2a : v3a;
        float rA = kA + __shfl_xor_sync(FULL, sA, 1);
        float rB = kB + __shfl_xor_sync(FULL, sB, 1);
        float k2 = bit1 ? rB : rA, s2 = bit1 ? rA : rB;
        float a = k2 + __shfl_xor_sync(FULL, s2, 2);    // bucket hl&3
        a += __shfl_xor_sync(FULL, a, 4);
        a += __shfl_xor_sync(FULL, a, 8);
        float b0 = __shfl_sync(FULL, a, base + 0);
        float b1 = __shfl_sync(FULL, a, base + 1);
        float b2 = __shfl_sync(FULL, a, base + 2);
        float b3 = __shfl_sync(FULL, a, base + 3);
        float sc = alpha * rcpa(S01 * S2n);
        float o = off3;
        lq[1][0] = fmaf(oma, lq[1][0] - o, sc * b0);
        lq[1][1] = fmaf(oma, lq[1][1] - o, sc * b1);
        lq[1][2] = fmaf(oma, lq[1][2] - o, sc * b2);
        lq[1][3] = fmaf(oma, lq[1][3] - o, sc * b3);
        off3 = rowmax4(lq[1]);
    }

    // ---- Output: rows 0,1 gathered from distributed lanes; rows 2,3 from regs ----
    float x0 = __shfl_sync(FULL, d0, base + 0);
    float x1 = __shfl_sync(FULL, d0, base + 4);
    float x2 = __shfl_sync(FULL, d0, base + 8);
    float x3 = __shfl_sync(FULL, d0, base + 12);
    float y0 = __shfl_sync(FULL, d1, base + 0);
    float y1 = __shfl_sync(FULL, d1, base + 1);
    float y2 = __shfl_sync(FULL, d1, base + 2);
    float y3 = __shfl_sync(FULL, d1, base + 3);
    float r0 = qsel(x0, y0, lq[0][0]-off2, lq[1][0]-off3, hl) * LN2;
    float r1 = qsel(x1, y1, lq[0][1]-off2, lq[1][1]-off3, hl) * LN2;
    float r2 = qsel(x2, y2, lq[0][2]-off2, lq[1][2]-off3, hl) * LN2;
    float r3 = qsel(x3, y3, lq[0][3]-off2, lq[1][3]-off3, hl) * LN2;
    if (hl < 4) {
        reinterpret_cast<float4*>(out)[(size_t)b * 4 + hl] = make_float4(r0, r1, r2, r3);
    }
}

extern "C" void kernel_launch(void* const* d_in, const int* in_sizes, int n_in,
                              void* d_out, int out_size)
{
    const float* log_qi    = (const float*)d_in[0]; // (N,4,4)
    const float* G         = (const float*)d_in[1]; // (N,8,4)
    const float* sqrt_2rho = (const float*)d_in[2]; // (N,)
    // d_in[3] = n_var, unused by reference
    const float* alpha     = (const float*)d_in[4]; // scalar

    float* out = (float*)d_out;

    // 2 items per warp -> NB/2 warps
    const int threads = 128;
    const int blocks  = (NB / 2) * 32 / threads;   // 4096
    mfnet_layer_kernel<<<blocks, threads>>>(log_qi, G, sqrt_2rho, alpha, out);
}

// round 12
// speedup vs baseline: 1.1115x; 1.1115x over previous
#include <cuda_runtime.h>

#define NB    32768
#define N_RX  8

// SYMS = {-3,-1,1,3}/sqrt(5)
#define S_M3 (-1.3416407864998738f)
#define S_M1 (-0.44721359549995793f)
#define S_P1 ( 0.44721359549995793f)
#define S_P3 ( 1.3416407864998738f)
#define LOG2E 1.4426950408889634f
#define LN2   0.6931471805599453f

typedef unsigned long long u64;

__device__ __forceinline__ float qsel(float a, float b, float c, float d, int i) {
    float ab = (i & 1) ? b : a;
    float cd = (i & 1) ? d : c;
    return (i & 2) ? cd : ab;
}
// rho2n*SY[i] from rm3=rho2n*S_M3, rm1=rho2n*S_M1 (SY[2]=-SY[1], SY[3]=-SY[0])
__device__ __forceinline__ float qselrn(float rm3, float rm1, int i) {
    float ab = (i & 1) ? rm1 : rm3;
    float cd = (i & 1) ? -rm3 : -rm1;
    return (i & 2) ? cd : ab;
}
__device__ __forceinline__ float rowmax4(const float* v) {
    return fmaxf(fmaxf(v[0], v[1]), fmaxf(v[2], v[3]));
}
__device__ __forceinline__ float ex2a(float x) {
    float y; asm("ex2.approx.ftz.f32 %0, %1;" : "=f"(y) : "f"(x)); return y;
}
__device__ __forceinline__ float lg2a(float x) {
    float y; asm("lg2.approx.ftz.f32 %0, %1;" : "=f"(y) : "f"(x)); return y;
}
__device__ __forceinline__ float rcpa(float x) {
    float y; asm("rcp.approx.ftz.f32 %0, %1;" : "=f"(y) : "f"(x)); return y;
}
// multiply + saturate to [0,1] in ONE instruction (FMUL.SAT); v>=0 so sat == min(v,1)
__device__ __forceinline__ float mulsat(float a, float b) {
    float y; asm("mul.rn.sat.f32 %0, %1, %2;" : "=f"(y) : "f"(a), "f"(b)); return y;
}
__device__ __forceinline__ u64 pk2(float lo, float hi) {
    u64 d; asm("mov.b64 %0, {%1, %2};" : "=l"(d) : "f"(lo), "f"(hi)); return d;
}
__device__ __forceinline__ void upk2(float& lo, float& hi, u64 d) {
    asm("mov.b64 {%0, %1}, %2;" : "=f"(lo), "=f"(hi) : "l"(d));
}
__device__ __forceinline__ u64 mul2(u64 a, u64 b) {
    u64 d; asm("mul.rn.f32x2 %0, %1, %2;" : "=l"(d) : "l"(a), "l"(b)); return d;
}
__device__ __forceinline__ u64 fma2(u64 a, u64 b, u64 c) {
    u64 d; asm("fma.rn.f32x2 %0, %1, %2, %3;" : "=l"(d) : "l"(a), "l"(b), "l"(c)); return d;
}

__global__ __launch_bounds__(128, 7)
void mfnet_layer_kernel(const float* __restrict__ log_qi_in,
                        const float* __restrict__ G,
                        const float* __restrict__ sqrt_2rho,
                        const float* __restrict__ alpha_ptr,
                        float* __restrict__ out)
{
    const int gtid = blockIdx.x * blockDim.x + threadIdx.x;
    const int w    = gtid >> 5;
    const int lane = gtid & 31;
    // Two items per warp: half-warps own item b = 2w + half.
    const int half = lane >> 4;
    const int hl   = lane & 15;
    const int b    = 2 * w + half;
    const int base = lane & 16;          // half-warp base lane for broadcasts

    const float alpha = __ldg(alpha_ptr);
    const float rho2  = __ldg(&sqrt_2rho[b]) * LOG2E;   // log2 units
    const float rho2n = -rho2;

    // k = i0*64 + i1*16 + i2*4 + i3 ; k = hl*16 + j
    const int i0 = hl >> 2;
    const int i1 = hl & 3;
    const int bit0 = hl & 1;
    const int bit1 = (hl >> 1) & 1;

    const float rm3 = rho2n * S_M3;
    const float rm1 = rho2n * S_M1;
    const float rs0 = qselrn(rm3, rm1, i0);
    const float rs1 = qselrn(rm3, rm1, i1);

    // ---- Laplace (log2 units), exp-factorized; sat-mul fuses clamp into the A*C multiply ----
    // xn = -x = t_{i2} + cb*m(i3); 2^{xn} = A_{i2} * C_{i3}
    // e = sat(A*C) = min(A*C, 1);  mterm = e*(1-0.5e);  lp2[j] = Sum_r x + log2(Prod_r mterm)
    const u64 NH2  = pk2(-0.5f, -0.5f);
    const u64 ONE2 = pk2(1.0f, 1.0f);
    u64 prod2[8] = {ONE2, ONE2, ONE2, ONE2, ONE2, ONE2, ONE2, ONE2};
    float SB = 0.f, SGZ = 0.f, SGW = 0.f;
    const float4* Gv = reinterpret_cast<const float4*>(G) + (size_t)b * N_RX;
    #pragma unroll
    for (int r = 0; r < N_RX; r++) {
        float4 g = Gv[r];
        float basen = fmaf(g.x, rs0, g.y * rs1);
        SB += basen; SGZ += g.z; SGW += g.w;
        float t0 = fmaf( g.z, rm3, basen);      // rho2n*S_M3
        float t1 = fmaf( g.z, rm1, basen);      // rho2n*S_M1
        float t2 = fmaf(-g.z, rm1, basen);      // rho2n*S_P1 (operand neg, free)
        float t3 = fmaf(-g.z, rm3, basen);      // rho2n*S_P3
        float cb = g.w * rm1;                   // D = 2^{g.w*rho2n*S_M1}
        float A0 = ex2a(t0), A1 = ex2a(t1), A2 = ex2a(t2), A3 = ex2a(t3);
        float D  = ex2a(cb), iD = rcpa(D);
        float D3 = (D * D) * D, iD3 = (iD * iD) * iD;
        const float As[4] = {A0, A1, A2, A3};
        const float Cs[4] = {D3, D, iD, iD3};   // C_{i3} = 2^{c3n*SY[i3]}
        #pragma unroll
        for (int p = 0; p < 8; p++) {          // p = i2*2 + (i3>>1)
            float A = As[p >> 1];
            float elo = mulsat(A, Cs[(p & 1) * 2]);
            float ehi = mulsat(A, Cs[(p & 1) * 2 + 1]);
            u64 e2 = pk2(elo, ehi);
            u64 h2 = fma2(NH2, e2, ONE2);
            prod2[p] = mul2(prod2[p], mul2(e2, h2));
        }
    }
    const float Cp  = rho2 * SGW;
    const float qz  = SGZ * rho2;
    const float nSB = -SB;
    const float SY[4] = {S_M3, S_M1, S_P1, S_P3};   // immediates
    float lp2[16];
    #pragma unroll
    for (int p = 0; p < 8; p++) {
        const int i2  = p >> 1;
        const int i3a = (p & 1) * 2;
        float T = fmaf(qz, SY[i2], nSB);            // = -Sum_r t_{i2}
        float plo, phi;
        upk2(plo, phi, prod2[p]);
        lp2[i2 * 4 + i3a]     = fmaf(Cp, SY[i3a],     T) + lg2a(fmaxf(plo, 1e-37f));
        lp2[i2 * 4 + i3a + 1] = fmaf(Cp, SY[i3a + 1], T) + lg2a(fmaxf(phi, 1e-37f));
    }

    const unsigned FULL = 0xffffffffu;
    const float oma = 1.0f - alpha;
    const float4* Lv = reinterpret_cast<const float4*>(log_qi_in) + (size_t)b * 4;

    // ---- Rows 0,1: distributed (each lane keeps only its own-index value) ----
    float4 v0 = Lv[0];
    float lq0own = qsel(v0.x, v0.y, v0.z, v0.w, i0) * LOG2E;
    float f0 = ex2a(lq0own);               // raw row, matches reference iter-0
    float4 v1 = Lv[1];
    float lq1own = qsel(v1.x, v1.y, v1.z, v1.w, i1) * LOG2E;
    float m1 = lq1own;                     // rowmax over i1 (bits 0,1)
    m1 = fmaxf(m1, __shfl_xor_sync(FULL, m1, 1));
    m1 = fmaxf(m1, __shfl_xor_sync(FULL, m1, 2));
    float f1 = ex2a(lq1own - m1);
    float S1 = f1 + __shfl_xor_sync(FULL, f1, 1);
    S1 += __shfl_xor_sync(FULL, S1, 2);

    // ---- Rows 2,3: full replication ----
    float lq[2][4], off2, off3;
    {
        float4 v = Lv[2];
        lq[0][0] = v.x * LOG2E; lq[0][1] = v.y * LOG2E;
        lq[0][2] = v.z * LOG2E; lq[0][3] = v.w * LOG2E;
        off2 = rowmax4(lq[0]);
    }
    {
        float4 v = Lv[3];
        lq[1][0] = v.x * LOG2E; lq[1][1] = v.y * LOG2E;
        lq[1][2] = v.z * LOG2E; lq[1][3] = v.w * LOG2E;
        off3 = rowmax4(lq[1]);
    }
    float e2n[4], S2, S3, ul[4];
    e2n[0] = ex2a(lq[0][0]-off2); e2n[1] = ex2a(lq[0][1]-off2);
    e2n[2] = ex2a(lq[0][2]-off2); e2n[3] = ex2a(lq[0][3]-off2);
    S2 = (e2n[0] + e2n[1]) + (e2n[2] + e2n[3]);
    {
        float e0 = ex2a(lq[1][0]-off3), e1 = ex2a(lq[1][1]-off3);
        float e2 = ex2a(lq[1][2]-off3), e3 = ex2a(lq[1][3]-off3);
        S3 = (e0 + e1) + (e2 + e3);
        #pragma unroll
        for (int c = 0; c < 4; c++)
            ul[c] = fmaf(e3, lp2[c*4+3], fmaf(e2, lp2[c*4+2], fmaf(e1, lp2[c*4+1], e0 * lp2[c*4+0])));
    }
    float sum_wl = fmaf(e2n[3], ul[3], fmaf(e2n[2], ul[2], fmaf(e2n[1], ul[1], e2n[0] * ul[0])));
    float S23 = S2 * S3;

    // ---- xi = 0 : bucket i0 (bits 2,3); reduce bits 0,1. Distributed update. ----
    float d0, S0n;
    {
        float a = f1 * sum_wl;
        a += __shfl_xor_sync(FULL, a, 1);
        a += __shfl_xor_sync(FULL, a, 2);          // own-bucket total in every lane
        float sc = alpha * rcpa(S1 * S23);
        float nv = fmaf(oma, lq0own, sc * a);
        float o = nv;
        o = fmaxf(o, __shfl_xor_sync(FULL, o, 4));
        o = fmaxf(o, __shfl_xor_sync(FULL, o, 8));
        d0 = nv - o;
        f0 = ex2a(d0);
        S0n = f0 + __shfl_xor_sync(FULL, f0, 4);
        S0n += __shfl_xor_sync(FULL, S0n, 8);
    }

    // ---- xi = 1 : bucket i1 (bits 0,1); reduce bits 2,3. Distributed update. ----
    float d1, S1n, f01;
    {
        float a = f0 * sum_wl;
        a += __shfl_xor_sync(FULL, a, 4);
        a += __shfl_xor_sync(FULL, a, 8);
        float sc = alpha * rcpa(S0n * S23);
        float nv = fmaf(oma, lq1own - m1, sc * a);
        float o = nv;
        o = fmaxf(o, __shfl_xor_sync(FULL, o, 1));
        o = fmaxf(o, __shfl_xor_sync(FULL, o, 2));
        d1 = nv - o;
        float e1n = ex2a(d1);
        S1n = e1n + __shfl_xor_sync(FULL, e1n, 1);
        S1n += __shfl_xor_sync(FULL, S1n, 2);
        f01 = f0 * e1n;
    }

    // ---- xi = 2 : bucket i2; fold onto hl bits 0,1, reduce bits 2,3. Full row. ----
    float e2w[4], S2n, S01;
    {
        float a0 = f01 * ul[0], a1 = f01 * ul[1], a2v = f01 * ul[2], a3v = f01 * ul[3];
        float kA = bit0 ? a1 : a0,   sA = bit0 ? a0 : a1;
        float kB = bit0 ? a3v : a2v, sB = bit0 ? a2v : a3v;
        float rA = kA + __shfl_xor_sync(FULL, sA, 1);
        float rB = kB + __shfl_xor_sync(FULL, sB, 1);
        float k2 = bit1 ? rB : rA,   s2 = bit1 ? rA : rB;
        float a = k2 + __shfl_xor_sync(FULL, s2, 2);    // bucket hl&3
        a += __shfl_xor_sync(FULL, a, 4);
        a += __shfl_xor_sync(FULL, a, 8);
        float b0 = __shfl_sync(FULL, a, base + 0);
        float b1 = __shfl_sync(FULL, a, base + 1);
        float b2 = __shfl_sync(FULL, a, base + 2);
        float b3 = __shfl_sync(FULL, a, base + 3);
        S01 = S0n * S1n;
        float sc = alpha * rcpa(S01 * S3);
        float o = off2;
        lq[0][0] = fmaf(oma, lq[0][0] - o, sc * b0);
        lq[0][1] = fmaf(oma, lq[0][1] - o, sc * b1);
        lq[0][2] = fmaf(oma, lq[0][2] - o, sc * b2);
        lq[0][3] = fmaf(oma, lq[0][3] - o, sc * b3);
        off2 = rowmax4(lq[0]);
        e2w[0] = ex2a(lq[0][0]-off2); e2w[1] = ex2a(lq[0][1]-off2);
        e2w[2] = ex2a(lq[0][2]-off2); e2w[3] = ex2a(lq[0][3]-off2);
        S2n = (e2w[0] + e2w[1]) + (e2w[2] + e2w[3]);
    }

    // ---- xi = 3 : bucket i3; fold + reduce bits 2,3. Full row. ----
    {
        float v0a = 0.f, v1a = 0.f, v2a = 0.f, v3a = 0.f;
        #pragma unroll
        for (int c = 0; c < 4; c++) {
            v0a = fmaf(e2w[c], lp2[c*4+0], v0a);
            v1a = fmaf(e2w[c], lp2[c*4+1], v1a);
            v2a = fmaf(e2w[c], lp2[c*4+2], v2a);
            v3a = fmaf(e2w[c], lp2[c*4+3], v3a);
        }
        v0a *= f01; v1a *= f01; v2a *= f01; v3a *= f01;
        float kA = bit0 ? v1a : v0a, sA = bit0 ? v0a : v1a;
        float kB = bit0 ? v3a : v2a, sB = bit0 ? v2a : v3a;
        float rA = kA + __shfl_xor_sync(FULL, sA, 1);
        float rB = kB + __shfl_xor_sync(FULL, sB, 1);
        float k2 = bit1 ? rB : rA, s2 = bit1 ? rA : rB;
        float a = k2 + __shfl_xor_sync(FULL, s2, 2);    // bucket hl&3
        a += __shfl_xor_sync(FULL, a, 4);
        a += __shfl_xor_sync(FULL, a, 8);
        float b0 = __shfl_sync(FULL, a, base + 0);
        float b1 = __shfl_sync(FULL, a, base + 1);
        float b2 = __shfl_sync(FULL, a, base + 2);
        float b3 = __shfl_sync(FULL, a, base + 3);
        float sc = alpha * rcpa(S01 * S2n);
        float o = off3;
        lq[1][0] = fmaf(oma, lq[1][0] - o, sc * b0);
        lq[1][1] = fmaf(oma, lq[1][1] - o, sc * b1);
        lq[1][2] = fmaf(oma, lq[1][2] - o, sc * b2);
        lq[1][3] = fmaf(oma, lq[1][3] - o, sc * b3);
        off3 = rowmax4(lq[1]);
    }

    // ---- Output: rows 0,1 gathered from distributed lanes; rows 2,3 from regs ----
    float x0 = __shfl_sync(FULL, d0, base + 0);
    float x1 = __shfl_sync(FULL, d0, base + 4);
    float x2 = __shfl_sync(FULL, d0, base + 8);
    float x3 = __shfl_sync(FULL, d0, base + 12);
    float y0 = __shfl_sync(FULL, d1, base + 0);
    float y1 = __shfl_sync(FULL, d1, base + 1);
    float y2 = __shfl_sync(FULL, d1, base + 2);
    float y3 = __shfl_sync(FULL, d1, base + 3);
    float r0 = qsel(x0, y0, lq[0][0]-off2, lq[1][0]-off3, hl) * LN2;
    float r1 = qsel(x1, y1, lq[0][1]-off2, lq[1][1]-off3, hl) * LN2;
    float r2 = qsel(x2, y2, lq[0][2]-off2, lq[1][2]-off3, hl) * LN2;
    float r3 = qsel(x3, y3, lq[0][3]-off2, lq[1][3]-off3, hl) * LN2;
    if (hl < 4) {
        reinterpret_cast<float4*>(out)[(size_t)b * 4 + hl] = make_float4(r0, r1, r2, r3);
    }
}

extern "C" void kernel_launch(void* const* d_in, const int* in_sizes, int n_in,
                              void* d_out, int out_size)
{
    const float* log_qi    = (const float*)d_in[0]; // (N,4,4)
    const float* G         = (const float*)d_in[1]; // (N,8,4)
    const float* sqrt_2rho = (const float*)d_in[2]; // (N,)
    // d_in[3] = n_var, unused by reference
    const float* alpha     = (const float*)d_in[4]; // scalar

    float* out = (float*)d_out;

    // 2 items per warp -> NB/2 warps
    const int threads = 128;
    const int blocks  = (NB / 2) * 32 / threads;   // 4096
    mfnet_layer_kernel<<<blocks, threads>>>(log_qi, G, sqrt_2rho, alpha, out);
}